// round 1
// baseline (speedup 1.0000x reference)
#include <cuda_runtime.h>
#include <cstdint>

#define K_DIM   8192
#define B_DIM   256
#define OUT_DIM 8192
#define BM 128
#define BN 128
#define BK 16
#define PAD 132                 // BK-row stride in floats (16B aligned, conflict-reduced)
#define NTILES (K_DIM / BK)     // 512

typedef unsigned long long u64;

__device__ __forceinline__ u64 pack2(float lo, float hi) {
    u64 r;
    asm("mov.b64 %0, {%1, %2};" : "=l"(r) : "f"(lo), "f"(hi));
    return r;
}
__device__ __forceinline__ void unpack2(u64 v, float& lo, float& hi) {
    asm("mov.b64 {%0, %1}, %2;" : "=f"(lo), "=f"(hi) : "l"(v));
}
// Packed 2xfp32 FMA (Blackwell FFMA2) — exact fp32 semantics on both lanes.
__device__ __forceinline__ void ffma2(u64& d, u64 a, u64 b) {
    asm("fma.rn.f32x2 %0, %1, %2, %0;" : "+l"(d) : "l"(a), "l"(b));
}

__global__ __launch_bounds__(256, 2)
void abstract_linear_kernel(const float* __restrict__ x,
                            const float* __restrict__ low,
                            const float* __restrict__ high,
                            const float* __restrict__ W,
                            const float* __restrict__ bias,
                            float* __restrict__ y,
                            float* __restrict__ low_out,
                            float* __restrict__ high_out)
{
    __shared__ __align__(16) float As[2][BK][PAD];
    __shared__ __align__(16) float Bs[2][BK][PAD];

    const int tid   = threadIdx.x;
    const int nBase = blockIdx.x * BN;
    const int mBase = blockIdx.y * BM;
    const bool doBounds = (blockIdx.y == 0);

    // Global->smem loader mapping: each thread owns 2 rows (lr, lr+64), one
    // 4-wide k chunk (lk) per BK tile, for both x and W.
    const int lr = tid >> 2;          // 0..63
    const int lk = (tid & 3) << 2;    // 0,4,8,12

    const float* xg0 = x + (size_t)(mBase + lr) * K_DIM + lk;
    const float* xg1 = xg0 + (size_t)64 * K_DIM;
    const float* wg0 = W + (size_t)(nBase + lr) * K_DIM + lk;
    const float* wg1 = wg0 + (size_t)64 * K_DIM;

    float4 fa0, fa1, fw0, fw1;                 // prefetch registers
    float lo0 = 0.f, lo1 = 0.f, hi0 = 0.f, hi1 = 0.f;  // fused IBP partials

    u64 acc[8][4];                             // 8 m-rows x 4 packed n-pairs
    #pragma unroll
    for (int i = 0; i < 8; ++i)
        #pragma unroll
        for (int j = 0; j < 4; ++j) acc[i][j] = 0ull;

    const int ty = tid >> 4;   // 0..15  (m direction)
    const int tx = tid & 15;   // 0..15  (n direction)

    auto fetch = [&](int kt) {
        const int off = kt * BK;
        fa0 = *reinterpret_cast<const float4*>(xg0 + off);
        fa1 = *reinterpret_cast<const float4*>(xg1 + off);
        fw0 = *reinterpret_cast<const float4*>(wg0 + off);
        fw1 = *reinterpret_cast<const float4*>(wg1 + off);
    };

    auto stash = [&](int buf, int kt) {
        if (doBounds) {
            const int kk = kt * BK + lk;
            const float4 l4 = *reinterpret_cast<const float4*>(low + kk);
            const float4 h4 = *reinterpret_cast<const float4*>(high + kk);
            float wp, wn;
            wp = fmaxf(fw0.x, 0.f); wn = fminf(fw0.x, 0.f);
            lo0 += wp * l4.x + wn * h4.x; hi0 += wp * h4.x + wn * l4.x;
            wp = fmaxf(fw0.y, 0.f); wn = fminf(fw0.y, 0.f);
            lo0 += wp * l4.y + wn * h4.y; hi0 += wp * h4.y + wn * l4.y;
            wp = fmaxf(fw0.z, 0.f); wn = fminf(fw0.z, 0.f);
            lo0 += wp * l4.z + wn * h4.z; hi0 += wp * h4.z + wn * l4.z;
            wp = fmaxf(fw0.w, 0.f); wn = fminf(fw0.w, 0.f);
            lo0 += wp * l4.w + wn * h4.w; hi0 += wp * h4.w + wn * l4.w;

            wp = fmaxf(fw1.x, 0.f); wn = fminf(fw1.x, 0.f);
            lo1 += wp * l4.x + wn * h4.x; hi1 += wp * h4.x + wn * l4.x;
            wp = fmaxf(fw1.y, 0.f); wn = fminf(fw1.y, 0.f);
            lo1 += wp * l4.y + wn * h4.y; hi1 += wp * h4.y + wn * l4.y;
            wp = fmaxf(fw1.z, 0.f); wn = fminf(fw1.z, 0.f);
            lo1 += wp * l4.z + wn * h4.z; hi1 += wp * h4.z + wn * l4.z;
            wp = fmaxf(fw1.w, 0.f); wn = fminf(fw1.w, 0.f);
            lo1 += wp * l4.w + wn * h4.w; hi1 += wp * h4.w + wn * l4.w;
        }
        // transpose into smem: [k][m] / [k][n]
        As[buf][lk + 0][lr]      = fa0.x; As[buf][lk + 1][lr]      = fa0.y;
        As[buf][lk + 2][lr]      = fa0.z; As[buf][lk + 3][lr]      = fa0.w;
        As[buf][lk + 0][lr + 64] = fa1.x; As[buf][lk + 1][lr + 64] = fa1.y;
        As[buf][lk + 2][lr + 64] = fa1.z; As[buf][lk + 3][lr + 64] = fa1.w;
        Bs[buf][lk + 0][lr]      = fw0.x; Bs[buf][lk + 1][lr]      = fw0.y;
        Bs[buf][lk + 2][lr]      = fw0.z; Bs[buf][lk + 3][lr]      = fw0.w;
        Bs[buf][lk + 0][lr + 64] = fw1.x; Bs[buf][lk + 1][lr + 64] = fw1.y;
        Bs[buf][lk + 2][lr + 64] = fw1.z; Bs[buf][lk + 3][lr + 64] = fw1.w;
    };

    // Prologue
    fetch(0);
    stash(0, 0);
    __syncthreads();

    int buf = 0;
    #pragma unroll 1
    for (int t = 0; t < NTILES; ++t) {
        if (t + 1 < NTILES) fetch(t + 1);

        #pragma unroll
        for (int kk = 0; kk < BK; ++kk) {
            const float4 a0 = *reinterpret_cast<const float4*>(&As[buf][kk][ty * 8]);
            const float4 a1 = *reinterpret_cast<const float4*>(&As[buf][kk][ty * 8 + 4]);
            const ulonglong2 bq0 = *reinterpret_cast<const ulonglong2*>(&Bs[buf][kk][tx * 8]);
            const ulonglong2 bq1 = *reinterpret_cast<const ulonglong2*>(&Bs[buf][kk][tx * 8 + 4]);
            const u64 bp0 = bq0.x, bp1 = bq0.y, bp2 = bq1.x, bp3 = bq1.y;
            const float am[8] = {a0.x, a0.y, a0.z, a0.w, a1.x, a1.y, a1.z, a1.w};
            #pragma unroll
            for (int i = 0; i < 8; ++i) {
                const u64 ap = pack2(am[i], am[i]);
                ffma2(acc[i][0], ap, bp0);
                ffma2(acc[i][1], ap, bp1);
                ffma2(acc[i][2], ap, bp2);
                ffma2(acc[i][3], ap, bp3);
            }
        }

        if (t + 1 < NTILES) {
            stash(buf ^ 1, t + 1);
            __syncthreads();
            buf ^= 1;
        }
    }

    // ---- epilogue: y = acc + bias ----
    const int gm = mBase + ty * 8;
    const int gn = nBase + tx * 8;
    const float4 bv0 = *reinterpret_cast<const float4*>(bias + gn);
    const float4 bv1 = *reinterpret_cast<const float4*>(bias + gn + 4);
    #pragma unroll
    for (int i = 0; i < 8; ++i) {
        float c0, c1, c2, c3, c4, c5, c6, c7;
        unpack2(acc[i][0], c0, c1);
        unpack2(acc[i][1], c2, c3);
        unpack2(acc[i][2], c4, c5);
        unpack2(acc[i][3], c6, c7);
        float4 o0 = make_float4(c0 + bv0.x, c1 + bv0.y, c2 + bv0.z, c3 + bv0.w);
        float4 o1 = make_float4(c4 + bv1.x, c5 + bv1.y, c6 + bv1.z, c7 + bv1.w);
        float* dst = y + (size_t)(gm + i) * OUT_DIM + gn;
        *reinterpret_cast<float4*>(dst)     = o0;
        *reinterpret_cast<float4*>(dst + 4) = o1;
    }

    // ---- epilogue: bounds (deterministic width-4 shuffle reduction) ----
    if (doBounds) {
        lo0 += __shfl_down_sync(0xffffffffu, lo0, 2, 4);
        lo0 += __shfl_down_sync(0xffffffffu, lo0, 1, 4);
        hi0 += __shfl_down_sync(0xffffffffu, hi0, 2, 4);
        hi0 += __shfl_down_sync(0xffffffffu, hi0, 1, 4);
        lo1 += __shfl_down_sync(0xffffffffu, lo1, 2, 4);
        lo1 += __shfl_down_sync(0xffffffffu, lo1, 1, 4);
        hi1 += __shfl_down_sync(0xffffffffu, hi1, 2, 4);
        hi1 += __shfl_down_sync(0xffffffffu, hi1, 1, 4);
        if ((tid & 3) == 0) {
            const int r0 = nBase + (tid >> 2);
            const int r1 = r0 + 64;
            low_out[r0]  = lo0 + bias[r0];
            high_out[r0] = hi0 + bias[r0];
            low_out[r1]  = lo1 + bias[r1];
            high_out[r1] = hi1 + bias[r1];
        }
    }
}

extern "C" void kernel_launch(void* const* d_in, const int* in_sizes, int n_in,
                              void* d_out, int out_size) {
    const float* x    = (const float*)d_in[0];
    const float* low  = (const float*)d_in[1];
    const float* high = (const float*)d_in[2];
    const float* W    = (const float*)d_in[3];
    const float* bias = (const float*)d_in[4];

    float* y        = (float*)d_out;                       // [256, 8192]
    float* low_out  = y + (size_t)B_DIM * OUT_DIM;         // [8192]
    float* high_out = low_out + OUT_DIM;                   // [8192]

    dim3 grid(OUT_DIM / BN, B_DIM / BM);  // (64, 2) = 128 CTAs
    abstract_linear_kernel<<<grid, 256>>>(x, low, high, W, bias, y, low_out, high_out);
}

// round 3
// speedup vs baseline: 1.8475x; 1.8475x over previous
#include <cuda_runtime.h>
#include <cuda_bf16.h>
#include <cstdint>

#define K_DIM   8192
#define B_DIM   256
#define OUT_DIM 8192
#define BM      128
#define BN      128
#define KC      32
#define NT      (K_DIM / KC)          // 256 k-stages
#define RSTRIDE 80                    // bytes per smem tile row (32 bf16 + pad)
#define TILE_BYTES  (128 * RSTRIDE)   // 10240
#define STAGE_BYTES (4 * TILE_BYTES)  // A_hi | A_lo | B_hi | B_lo = 40960
#define DSMEM_BYTES (2 * STAGE_BYTES) // 81920

// ---------------- scratch: bf16 split of x ----------------
__device__ __nv_bfloat16 g_x_hi[(size_t)B_DIM * K_DIM];
__device__ __nv_bfloat16 g_x_lo[(size_t)B_DIM * K_DIM];

// ---------------- helpers ----------------
__device__ __forceinline__ uint32_t smem_u32(const void* p) {
    uint32_t a;
    asm("{ .reg .u64 t; cvta.to.shared.u64 t, %1; cvt.u32.u64 %0, t; }" : "=r"(a) : "l"(p));
    return a;
}
// pack two floats -> bf16x2 (hiVal -> upper 16 bits, loVal -> lower 16 bits)
__device__ __forceinline__ uint32_t cvt2(float hiVal, float loVal) {
    uint32_t r;
    asm("cvt.rn.bf16x2.f32 %0, %1, %2;" : "=r"(r) : "f"(hiVal), "f"(loVal));
    return r;
}

#define LDSM4(r0, r1, r2, r3, addr) \
    asm volatile("ldmatrix.sync.aligned.m8n8.x4.shared.b16 {%0,%1,%2,%3}, [%4];" \
                 : "=r"(r0), "=r"(r1), "=r"(r2), "=r"(r3) : "r"(addr))

#define MMA(c, a, b) \
    asm volatile("mma.sync.aligned.m16n8k16.row.col.f32.bf16.bf16.f32 " \
                 "{%0,%1,%2,%3}, {%4,%5,%6,%7}, {%8,%9}, {%0,%1,%2,%3};" \
                 : "+f"((c)[0]), "+f"((c)[1]), "+f"((c)[2]), "+f"((c)[3]) \
                 : "r"((a)[0]), "r"((a)[1]), "r"((a)[2]), "r"((a)[3]), \
                   "r"((b)[0]), "r"((b)[1]))

#define CP_ASYNC16(dst, src) \
    asm volatile("cp.async.cg.shared.global [%0], [%1], 16;" :: "r"(dst), "l"(src) : "memory")
#define CP_COMMIT() asm volatile("cp.async.commit_group;" ::: "memory")
#define CP_WAIT0()  asm volatile("cp.async.wait_group 0;" ::: "memory")

// ---------------- kernel 1: split x into bf16 hi/lo ----------------
__global__ __launch_bounds__(256)
void convert_x_kernel(const float* __restrict__ x) {
    size_t i = ((size_t)blockIdx.x * 256 + threadIdx.x) * 8;
    float4 a = *reinterpret_cast<const float4*>(x + i);
    float4 b = *reinterpret_cast<const float4*>(x + i + 4);
    uint32_t h0 = cvt2(a.y, a.x), h1 = cvt2(a.w, a.z);
    uint32_t h2 = cvt2(b.y, b.x), h3 = cvt2(b.w, b.z);
    float l0 = a.x - __uint_as_float(h0 << 16);
    float l1 = a.y - __uint_as_float(h0 & 0xffff0000u);
    float l2 = a.z - __uint_as_float(h1 << 16);
    float l3 = a.w - __uint_as_float(h1 & 0xffff0000u);
    float l4 = b.x - __uint_as_float(h2 << 16);
    float l5 = b.y - __uint_as_float(h2 & 0xffff0000u);
    float l6 = b.z - __uint_as_float(h3 << 16);
    float l7 = b.w - __uint_as_float(h3 & 0xffff0000u);
    *reinterpret_cast<uint4*>(g_x_hi + i) = make_uint4(h0, h1, h2, h3);
    *reinterpret_cast<uint4*>(g_x_lo + i) =
        make_uint4(cvt2(l1, l0), cvt2(l3, l2), cvt2(l5, l4), cvt2(l7, l6));
}

// ---------------- kernel 2: split-bf16 mma.sync GEMM + fused IBP ----------------
__global__ __launch_bounds__(256, 1)
void abstract_linear_mma_kernel(const float* __restrict__ low,
                                const float* __restrict__ high,
                                const float* __restrict__ W,
                                const float* __restrict__ bias,
                                float* __restrict__ y,
                                float* __restrict__ low_out,
                                float* __restrict__ high_out)
{
    extern __shared__ __align__(128) char dsm[];
    const uint32_t sbase = smem_u32(dsm);

    const int tid  = threadIdx.x;
    const int lane = tid & 31;
    const int wid  = tid >> 5;
    const int nBase = blockIdx.x * BN;
    const int mBase = blockIdx.y * BM;
    const bool doB = (blockIdx.y == 0);

    const int wm = wid >> 2;   // 0..1  (m direction, 64 rows each)
    const int wn = wid & 3;    // 0..3  (n direction, 32 cols each)

    // ---- loader mapping (W + bounds): thread -> (n-row, k half) ----
    const int lrow = tid >> 1;        // 0..127
    const int lkh  = tid & 1;         // k half (16 elems)
    const float* wg = W + (size_t)(nBase + lrow) * K_DIM + lkh * 16;
    const uint32_t wsts = (uint32_t)lrow * RSTRIDE + lkh * 32;

    // ---- loader mapping (x via cp.async): thread -> one tile row ----
    const int xrow = tid & 127;
    const bool isHi = (tid < 128);
    const __nv_bfloat16* xg = (isHi ? g_x_hi : g_x_lo) + (size_t)(mBase + xrow) * K_DIM;
    const uint32_t xsts = (isHi ? 0u : (uint32_t)TILE_BYTES) + (uint32_t)xrow * RSTRIDE;

    // ---- ldmatrix per-thread offsets within a stage ----
    const uint32_t aOff = (uint32_t)(wm * 64 + (lane & 15)) * RSTRIDE + (lane >> 4) * 16;
    const uint32_t bOff = (uint32_t)(wn * 32 + (lane & 7) + ((lane >> 4) & 1) * 8) * RSTRIDE
                        + ((lane >> 3) & 1) * 16;

    float acc[4][4][4];
    #pragma unroll
    for (int i = 0; i < 4; ++i)
        #pragma unroll
        for (int j = 0; j < 4; ++j)
            #pragma unroll
            for (int r = 0; r < 4; ++r) acc[i][j][r] = 0.f;

    float boundLo = 0.f, boundHi = 0.f;
    float4 wv[4];

    auto loadW = [&](int kt) {
        #pragma unroll
        for (int i = 0; i < 4; ++i)
            wv[i] = *reinterpret_cast<const float4*>(wg + (size_t)kt * KC + i * 4);
    };

    auto cpX = [&](int buf, int kt) {
        const uint32_t dst = sbase + buf * STAGE_BYTES + xsts;
        const __nv_bfloat16* src = xg + kt * KC;
        #pragma unroll
        for (int c = 0; c < 4; ++c) CP_ASYNC16(dst + c * 16, src + c * 8);
        CP_COMMIT();
    };

    auto stashW = [&](int buf, int kt) {
        char* bHp = dsm + (size_t)buf * STAGE_BYTES + 2 * TILE_BYTES + wsts;
        char* bLp = bHp + TILE_BYTES;
        #pragma unroll
        for (int i = 0; i < 2; ++i) {
            const float4 a = wv[2 * i], b = wv[2 * i + 1];
            uint32_t h0 = cvt2(a.y, a.x), h1 = cvt2(a.w, a.z);
            uint32_t h2 = cvt2(b.y, b.x), h3 = cvt2(b.w, b.z);
            float l0 = a.x - __uint_as_float(h0 << 16);
            float l1 = a.y - __uint_as_float(h0 & 0xffff0000u);
            float l2 = a.z - __uint_as_float(h1 << 16);
            float l3 = a.w - __uint_as_float(h1 & 0xffff0000u);
            float l4 = b.x - __uint_as_float(h2 << 16);
            float l5 = b.y - __uint_as_float(h2 & 0xffff0000u);
            float l6 = b.z - __uint_as_float(h3 << 16);
            float l7 = b.w - __uint_as_float(h3 & 0xffff0000u);
            *reinterpret_cast<uint4*>(bHp + i * 16) = make_uint4(h0, h1, h2, h3);
            *reinterpret_cast<uint4*>(bLp + i * 16) =
                make_uint4(cvt2(l1, l0), cvt2(l3, l2), cvt2(l5, l4), cvt2(l7, l6));
            if (doB) {
                const float* lp = low  + kt * KC + lkh * 16 + i * 8;
                const float* hp = high + kt * KC + lkh * 16 + i * 8;
                const float4 la = *reinterpret_cast<const float4*>(lp);
                const float4 lb = *reinterpret_cast<const float4*>(lp + 4);
                const float4 ha = *reinterpret_cast<const float4*>(hp);
                const float4 hb = *reinterpret_cast<const float4*>(hp + 4);
                float p, q;
                p = a.x * la.x; q = a.x * ha.x; boundLo += fminf(p, q); boundHi += fmaxf(p, q);
                p = a.y * la.y; q = a.y * ha.y; boundLo += fminf(p, q); boundHi += fmaxf(p, q);
                p = a.z * la.z; q = a.z * ha.z; boundLo += fminf(p, q); boundHi += fmaxf(p, q);
                p = a.w * la.w; q = a.w * ha.w; boundLo += fminf(p, q); boundHi += fmaxf(p, q);
                p = b.x * lb.x; q = b.x * hb.x; boundLo += fminf(p, q); boundHi += fmaxf(p, q);
                p = b.y * lb.y; q = b.y * hb.y; boundLo += fminf(p, q); boundHi += fmaxf(p, q);
                p = b.z * lb.z; q = b.z * hb.z; boundLo += fminf(p, q); boundHi += fmaxf(p, q);
                p = b.w * lb.w; q = b.w * hb.w; boundLo += fminf(p, q); boundHi += fmaxf(p, q);
            }
        }
    };

    auto doMMA = [&](int buf) {
        const uint32_t A_hi = sbase + buf * STAGE_BYTES;
        const uint32_t A_lo = A_hi + TILE_BYTES;
        const uint32_t B_hi = A_hi + 2 * TILE_BYTES;
        const uint32_t B_lo = A_hi + 3 * TILE_BYTES;
        #pragma unroll
        for (int k16 = 0; k16 < 2; ++k16) {
            uint32_t aH[4][4], aL[4][4], bH[4][2], bL[4][2];
            #pragma unroll
            for (int mf = 0; mf < 4; ++mf) {
                LDSM4(aH[mf][0], aH[mf][1], aH[mf][2], aH[mf][3],
                      A_hi + aOff + mf * (16 * RSTRIDE) + k16 * 32);
                LDSM4(aL[mf][0], aL[mf][1], aL[mf][2], aL[mf][3],
                      A_lo + aOff + mf * (16 * RSTRIDE) + k16 * 32);
            }
            #pragma unroll
            for (int p = 0; p < 2; ++p) {
                uint32_t r0, r1, r2, r3;
                LDSM4(r0, r1, r2, r3, B_hi + bOff + p * (16 * RSTRIDE) + k16 * 32);
                bH[2 * p][0] = r0; bH[2 * p][1] = r1;
                bH[2 * p + 1][0] = r2; bH[2 * p + 1][1] = r3;
                LDSM4(r0, r1, r2, r3, B_lo + bOff + p * (16 * RSTRIDE) + k16 * 32);
                bL[2 * p][0] = r0; bL[2 * p][1] = r1;
                bL[2 * p + 1][0] = r2; bL[2 * p + 1][1] = r3;
            }
            #pragma unroll
            for (int mf = 0; mf < 4; ++mf)
                #pragma unroll
                for (int nf = 0; nf < 4; ++nf) {
                    MMA(acc[mf][nf], aH[mf], bH[nf]);
                    MMA(acc[mf][nf], aH[mf], bL[nf]);
                    MMA(acc[mf][nf], aL[mf], bH[nf]);
                }
        }
    };

    // ---- prologue: stage 0 ----
    cpX(0, 0);
    loadW(0);
    stashW(0, 0);
    CP_WAIT0();
    __syncthreads();

    // ---- main loop ----
    #pragma unroll 1
    for (int kt = 0; kt < NT; ++kt) {
        const int buf = kt & 1;
        if (kt + 1 < NT) {
            cpX(buf ^ 1, kt + 1);
            loadW(kt + 1);
        }
        doMMA(buf);
        if (kt + 1 < NT) {
            stashW(buf ^ 1, kt + 1);
            CP_WAIT0();
            __syncthreads();
        }
    }

    // ---- epilogue: y = acc + bias ----
    #pragma unroll
    for (int mf = 0; mf < 4; ++mf) {
        const int r0 = mBase + wm * 64 + mf * 16 + (lane >> 2);
        #pragma unroll
        for (int nf = 0; nf < 4; ++nf) {
            const int c = nBase + wn * 32 + nf * 8 + (lane & 3) * 2;
            const float2 bv = *reinterpret_cast<const float2*>(bias + c);
            float2 o0 = make_float2(acc[mf][nf][0] + bv.x, acc[mf][nf][1] + bv.y);
            float2 o1 = make_float2(acc[mf][nf][2] + bv.x, acc[mf][nf][3] + bv.y);
            *reinterpret_cast<float2*>(y + (size_t)r0 * OUT_DIM + c) = o0;
            *reinterpret_cast<float2*>(y + (size_t)(r0 + 8) * OUT_DIM + c) = o1;
        }
    }

    // ---- epilogue: bounds ----
    if (doB) {
        boundLo += __shfl_xor_sync(0xffffffffu, boundLo, 1);
        boundHi += __shfl_xor_sync(0xffffffffu, boundHi, 1);
        if (lkh == 0) {
            const int r = nBase + lrow;
            const float bb = bias[r];
            low_out[r]  = boundLo + bb;
            high_out[r] = boundHi + bb;
        }
    }
}

extern "C" void kernel_launch(void* const* d_in, const int* in_sizes, int n_in,
                              void* d_out, int out_size) {
    const float* x    = (const float*)d_in[0];
    const float* low  = (const float*)d_in[1];
    const float* high = (const float*)d_in[2];
    const float* W    = (const float*)d_in[3];
    const float* bias = (const float*)d_in[4];

    float* y        = (float*)d_out;
    float* low_out  = y + (size_t)B_DIM * OUT_DIM;
    float* high_out = low_out + OUT_DIM;

    cudaFuncSetAttribute(abstract_linear_mma_kernel,
                         cudaFuncAttributeMaxDynamicSharedMemorySize, DSMEM_BYTES);

    convert_x_kernel<<<(B_DIM * K_DIM) / (256 * 8), 256>>>(x);

    dim3 grid(OUT_DIM / BN, B_DIM / BM);  // (64, 2)
    abstract_linear_mma_kernel<<<grid, 256, DSMEM_BYTES>>>(low, high, W, bias,
                                                           y, low_out, high_out);
}